// round 11
// baseline (speedup 1.0000x reference)
#include <cuda_runtime.h>
#include <cuda_fp16.h>

// Hopf oscillator CPG step, reformulated:
//   sin(psi_j - psi_i - phi_ij) = (s_j c_i - c_j s_i)cosφ - (c_j c_i + s_j s_i)sinφ
// A_ij = w_zd cosφ_zd, B_ij = w_zd sinφ_zd, x_j = r_j s_j, y_j = r_j c_j:
//   coupling_i = c_i*(A x - B y)_i - s_i*(A y + B x)_i
// R11 = R10 (23.0us) + occupancy push: hot kernel is full-tile only (no guards)
// under __launch_bounds__(256,5) -> 5 CTAs/SM (40 warps); guarded tail kernel
// covers any remainder rows (none for nrows=65536). Prep parallelized 8x128.

#define PI2F 6.28318530717958647692f

typedef unsigned long long u64;

__device__ __half2 gABh[1024];  // [j*32 + i] = half2{A[i][j], B[i][j]} (pre-transposed)
__device__ float   gTPV[32];    // 2*pi*V_MAX*sigmoid(v)
__device__ float   gBA[32];     // B_MAX*sigmoid(b)
__device__ float   gCA[32];     // C_MAX*sigmoid(c)

__device__ __forceinline__ u64 pack2(float lo, float hi) {
    u64 r;
    asm("mov.b64 %0, {%1, %2};" : "=l"(r) : "f"(lo), "f"(hi));
    return r;
}
__device__ __forceinline__ void unpack2(u64 v, float& lo, float& hi) {
    asm("mov.b64 {%0, %1}, %2;" : "=f"(lo), "=f"(hi) : "l"(v));
}
#define FMA2(acc, a, b) asm("fma.rn.f32x2 %0, %1, %2, %0;" : "+l"(acc) : "l"(a), "l"(b))

__device__ __forceinline__ float fsigmoid(float x) {
    return 1.0f / (1.0f + __expf(-x));
}

__global__ void prep_kernel(const float* __restrict__ v, const float* __restrict__ b,
                            const float* __restrict__ c, const float* __restrict__ w,
                            const float* __restrict__ phi) {
    int m = blockIdx.x * 128 + threadIdx.x;   // 0..1023, m = i*32 + j
    float A = 0.0f, Bv = 0.0f;
    if (m % 33 != 0) {              // zero-diag: diagonal iff m % 33 == 0
        int kk = m / 33;            // 0..30
        int jj = m % 33 - 1;        // 0..31
        float wa = fsigmoid(w[kk * 32 + jj]);           // W_MAX = 1
        float pa = PI2F * fsigmoid(phi[kk * 32 + jj]);  // PHI_MAX = 2*pi
        float sp, cp;
        __sincosf(pa, &sp, &cp);
        A  = wa * cp;
        Bv = wa * sp;
    }
    gABh[(m & 31) * 32 + (m >> 5)] = __floats2half2_rn(A, Bv);  // store [j][i]
    if (m < 32) {
        gTPV[m] = (PI2F * 5.0f) * fsigmoid(v[m]);
        gBA[m]  = 2.0f  * fsigmoid(b[m]);
        gCA[m]  = 10.0f * fsigmoid(c[m]);
    }
}

// ---------------- hot kernel: full 64-row tiles only, no guards ----------------
__global__ __launch_bounds__(256, 5)
void hopf_kernel(const float* __restrict__ in, float* __restrict__ out) {
    const int tid  = threadIdx.x;
    const int lane = tid & 31;          // oscillator index i
    const int wib  = tid >> 5;          // warp in block (0..7)

    __shared__ __half2 sAB[1024];       // [j*32 + i], lane-consecutive LDS.32
    __shared__ float4  sXY[8][2][32];   // per-warp {x0,x1,y0,y1} broadcast buffers

    // coalesced L2->smem copy of the prebuilt half2 matrix (4KB)
    {
        const float4* src = reinterpret_cast<const float4*>(gABh);
        float4*       dst = reinterpret_cast<float4*>(sAB);
        dst[tid] = src[tid];
    }

    const float tpv = gTPV[lane];
    const float ba  = gBA[lane];
    const float ca  = gCA[lane];

    __syncthreads();

    const int rowBase = (blockIdx.x * 8 + wib) * 8;   // 8 rows per warp

    #pragma unroll
    for (int q = 0; q < 2; q++) {
        const int r0 = rowBase + q * 4;
        float sv[4], cv[4], xv[4], yv[4];

        #pragma unroll
        for (int t = 0; t < 4; t++) {
            const float* rp = in + (size_t)(r0 + t) * 96;
            float psi = rp[lane];
            float rr  = rp[32 + lane];
            float rd  = rp[64 + lane];
            __sincosf(psi, &sv[t], &cv[t]);
            xv[t] = rr * sv[t];
            yv[t] = rr * cv[t];
            float rdd = ca * (0.25f * ca * (ba - rr) - rd);
            float* op = out + (size_t)(r0 + t) * 96;
            op[32 + lane] = rd;
            op[64 + lane] = rdd;
        }

        __syncwarp();   // previous quad's readers done before overwrite
        sXY[wib][0][lane] = make_float4(xv[0], xv[1], yv[0], yv[1]);
        sXY[wib][1][lane] = make_float4(xv[2], xv[3], yv[2], yv[3]);
        __syncwarp();

        // accumulators: P1=sum(Ax), P2=sum(By), Q1=sum(Ay), Q2=sum(Bx)
        u64 aP1 = 0, aP2 = 0, aQ1 = 0, aQ2 = 0;   // rows (0,1)
        u64 bP1 = 0, bP2 = 0, bQ1 = 0, bQ2 = 0;   // rows (2,3)

        #pragma unroll
        for (int j = 0; j < 32; j++) {
            __half2 h = sAB[j * 32 + lane];        // LDS.32, conflict-free (1 wf)
            float Af = __low2float(h);
            float Bf = __high2float(h);
            u64 AA = pack2(Af, Af);
            u64 BB = pack2(Bf, Bf);
            ulonglong2 p0 = *reinterpret_cast<const ulonglong2*>(&sXY[wib][0][j]);
            ulonglong2 p1 = *reinterpret_cast<const ulonglong2*>(&sXY[wib][1][j]);
            FMA2(aP1, AA, p0.x);  FMA2(aP2, BB, p0.y);
            FMA2(aQ1, AA, p0.y);  FMA2(aQ2, BB, p0.x);
            FMA2(bP1, AA, p1.x);  FMA2(bP2, BB, p1.y);
            FMA2(bQ1, AA, p1.y);  FMA2(bQ2, BB, p1.x);
        }

        float P[4], Q[4];
        {
            float l0,h0,l1,h1,l2,h2,l3,h3;
            unpack2(aP1,l0,h0); unpack2(aP2,l1,h1);
            unpack2(aQ1,l2,h2); unpack2(aQ2,l3,h3);
            P[0] = l0 - l1;  P[1] = h0 - h1;
            Q[0] = l2 + l3;  Q[1] = h2 + h3;
        }
        {
            float l0,h0,l1,h1,l2,h2,l3,h3;
            unpack2(bP1,l0,h0); unpack2(bP2,l1,h1);
            unpack2(bQ1,l2,h2); unpack2(bQ2,l3,h3);
            P[2] = l0 - l1;  P[3] = h0 - h1;
            Q[2] = l2 + l3;  Q[3] = h2 + h3;
        }

        #pragma unroll
        for (int t = 0; t < 4; t++)
            out[(size_t)(r0 + t) * 96 + lane] = tpv + cv[t] * P[t] - sv[t] * Q[t];
    }
}

// ---------------- guarded tail kernel (remainder rows; unused at 65536) --------
__global__ void hopf_tail(const float* __restrict__ in, float* __restrict__ out,
                          int rowStart, int nrows) {
    const int tid  = threadIdx.x;
    const int lane = tid & 31;
    const int wib  = tid >> 5;

    __shared__ __half2 sAB[1024];
    __shared__ float4  sXY[8][2][32];

    {
        const float4* src = reinterpret_cast<const float4*>(gABh);
        float4*       dst = reinterpret_cast<float4*>(sAB);
        dst[tid] = src[tid];
    }
    const float tpv = gTPV[lane];
    const float ba  = gBA[lane];
    const float ca  = gCA[lane];
    __syncthreads();

    const int rowBase = rowStart + wib * 8;

    #pragma unroll
    for (int q = 0; q < 2; q++) {
        const int r0 = rowBase + q * 4;
        float sv[4], cv[4], xv[4], yv[4];

        #pragma unroll
        for (int t = 0; t < 4; t++) {
            const int row = r0 + t;
            float psi = 0.0f, rr = 0.0f, rd = 0.0f;
            if (row < nrows) {
                const float* rp = in + (size_t)row * 96;
                psi = rp[lane];  rr = rp[32 + lane];  rd = rp[64 + lane];
            }
            __sincosf(psi, &sv[t], &cv[t]);
            xv[t] = rr * sv[t];
            yv[t] = rr * cv[t];
            if (row < nrows) {
                float rdd = ca * (0.25f * ca * (ba - rr) - rd);
                float* op = out + (size_t)row * 96;
                op[32 + lane] = rd;
                op[64 + lane] = rdd;
            }
        }

        __syncwarp();
        sXY[wib][0][lane] = make_float4(xv[0], xv[1], yv[0], yv[1]);
        sXY[wib][1][lane] = make_float4(xv[2], xv[3], yv[2], yv[3]);
        __syncwarp();

        u64 aP1 = 0, aP2 = 0, aQ1 = 0, aQ2 = 0;
        u64 bP1 = 0, bP2 = 0, bQ1 = 0, bQ2 = 0;

        #pragma unroll
        for (int j = 0; j < 32; j++) {
            __half2 h = sAB[j * 32 + lane];
            float Af = __low2float(h);
            float Bf = __high2float(h);
            u64 AA = pack2(Af, Af);
            u64 BB = pack2(Bf, Bf);
            ulonglong2 p0 = *reinterpret_cast<const ulonglong2*>(&sXY[wib][0][j]);
            ulonglong2 p1 = *reinterpret_cast<const ulonglong2*>(&sXY[wib][1][j]);
            FMA2(aP1, AA, p0.x);  FMA2(aP2, BB, p0.y);
            FMA2(aQ1, AA, p0.y);  FMA2(aQ2, BB, p0.x);
            FMA2(bP1, AA, p1.x);  FMA2(bP2, BB, p1.y);
            FMA2(bQ1, AA, p1.y);  FMA2(bQ2, BB, p1.x);
        }

        float P[4], Q[4];
        {
            float l0,h0,l1,h1,l2,h2,l3,h3;
            unpack2(aP1,l0,h0); unpack2(aP2,l1,h1);
            unpack2(aQ1,l2,h2); unpack2(aQ2,l3,h3);
            P[0] = l0 - l1;  P[1] = h0 - h1;
            Q[0] = l2 + l3;  Q[1] = h2 + h3;
        }
        {
            float l0,h0,l1,h1,l2,h2,l3,h3;
            unpack2(bP1,l0,h0); unpack2(bP2,l1,h1);
            unpack2(bQ1,l2,h2); unpack2(bQ2,l3,h3);
            P[2] = l0 - l1;  P[3] = h0 - h1;
            Q[2] = l2 + l3;  Q[3] = h2 + h3;
        }

        #pragma unroll
        for (int t = 0; t < 4; t++) {
            const int row = r0 + t;
            if (row < nrows)
                out[(size_t)row * 96 + lane] = tpv + cv[t] * P[t] - sv[t] * Q[t];
        }
    }
}

extern "C" void kernel_launch(void* const* d_in, const int* in_sizes, int n_in,
                              void* d_out, int out_size) {
    const float* states = (const float*)d_in[0];
    const float* v      = (const float*)d_in[1];
    const float* b      = (const float*)d_in[2];
    const float* c      = (const float*)d_in[3];
    const float* w      = (const float*)d_in[4];
    const float* phi    = (const float*)d_in[5];
    float* out = (float*)d_out;

    const int nrows = in_sizes[0] / 96;         // 65536
    prep_kernel<<<8, 128>>>(v, b, c, w, phi);

    const int fullBlocks = nrows / 64;          // 64 rows per 256-thread block
    if (fullBlocks > 0)
        hopf_kernel<<<fullBlocks, 256>>>(states, out);

    const int covered = fullBlocks * 64;
    if (covered < nrows)
        hopf_tail<<<1, 256>>>(states, out, covered, nrows);
}

// round 12
// speedup vs baseline: 1.1099x; 1.1099x over previous
#include <cuda_runtime.h>
#include <cuda_fp16.h>
#include <cstdint>

// Hopf oscillator CPG step, reformulated:
//   sin(psi_j - psi_i - phi_ij) = (s_j c_i - c_j s_i)cosφ - (c_j c_i + s_j s_i)sinφ
// A_ij = w_zd cosφ_zd, B_ij = w_zd sinφ_zd, x_j = r_j s_j, y_j = r_j c_j:
//   coupling_i = c_i*(A x - B y)_i - s_i*(A y + B x)_i
// R12: all-half2 inner loop. Matrix half2 {A,B} is a DIRECT HFMA2 operand:
//   accP {ΣAx,ΣBy} += {A,B}⊙{x,y};  P = lo - hi
//   accQ {ΣAy,ΣBx} += {A,B}⊙{y,x};  Q = lo + hi
// 11 instr / quad-j (vs 17), zero cvt/pack ALU, LDS->HFMA2 direct.
// Half accumulation split into two 16-term partials, combined in fp32.

#define PI2F 6.28318530717958647692f

__device__ __half2 gABh[1024];  // [j*32 + i] = half2{A[i][j], B[i][j]} (pre-transposed)
__device__ float   gTPV[32];    // 2*pi*V_MAX*sigmoid(v)
__device__ float   gBA[32];     // B_MAX*sigmoid(b)
__device__ float   gCA[32];     // C_MAX*sigmoid(c)

__device__ __forceinline__ float fsigmoid(float x) {
    return 1.0f / (1.0f + __expf(-x));
}

__global__ void prep_kernel(const float* __restrict__ v, const float* __restrict__ b,
                            const float* __restrict__ c, const float* __restrict__ w,
                            const float* __restrict__ phi) {
    int m = blockIdx.x * 128 + threadIdx.x;   // 0..1023, m = i*32 + j
    float A = 0.0f, Bv = 0.0f;
    if (m % 33 != 0) {              // zero-diag: diagonal iff m % 33 == 0
        int kk = m / 33;            // 0..30
        int jj = m % 33 - 1;        // 0..31
        float wa = fsigmoid(w[kk * 32 + jj]);           // W_MAX = 1
        float pa = PI2F * fsigmoid(phi[kk * 32 + jj]);  // PHI_MAX = 2*pi
        float sp, cp;
        __sincosf(pa, &sp, &cp);
        A  = wa * cp;
        Bv = wa * sp;
    }
    gABh[(m & 31) * 32 + (m >> 5)] = __floats2half2_rn(A, Bv);  // store [j][i]
    if (m < 32) {
        gTPV[m] = (PI2F * 5.0f) * fsigmoid(v[m]);
        gBA[m]  = 2.0f  * fsigmoid(b[m]);
        gCA[m]  = 10.0f * fsigmoid(c[m]);
    }
}

// ---------------- hot kernel: full 64-row tiles only, no guards ----------------
__global__ __launch_bounds__(256, 5)
void hopf_kernel(const float* __restrict__ in, float* __restrict__ out) {
    const int tid  = threadIdx.x;
    const int lane = tid & 31;          // oscillator index i
    const int wib  = tid >> 5;          // warp in block (0..7)

    __shared__ __half2 sAB[1024];       // [j*32 + i], lane-consecutive LDS.32
    __shared__ uint4   sXY[8][2][32];   // [warp][quad][osc j] = half2{x,y} for rows R0..R3
    __shared__ uint4   sYX[8][2][32];   // [warp][quad][osc j] = half2{y,x} for rows R0..R3

    // coalesced L2->smem copy of the prebuilt half2 matrix (4KB)
    {
        const float4* src = reinterpret_cast<const float4*>(gABh);
        float4*       dst = reinterpret_cast<float4*>(sAB);
        dst[tid] = src[tid];
    }

    const float tpv = gTPV[lane];
    const float ba  = gBA[lane];
    const float ca  = gCA[lane];

    __syncthreads();

    const int rowBase = (blockIdx.x * 8 + wib) * 8;   // 8 rows per warp

    #pragma unroll
    for (int q = 0; q < 2; q++) {
        const int r0 = rowBase + q * 4;
        float sv[4], cv[4];
        uint4 xy, yx;                   // 4 rows of half2 values, built in regs

        #pragma unroll
        for (int t = 0; t < 4; t++) {
            const float* rp = in + (size_t)(r0 + t) * 96;
            float psi = rp[lane];
            float rr  = rp[32 + lane];
            float rd  = rp[64 + lane];
            __sincosf(psi, &sv[t], &cv[t]);
            float x = rr * sv[t];
            float y = rr * cv[t];
            __half2 hxy = __floats2half2_rn(x, y);
            __half2 hyx = __floats2half2_rn(y, x);
            reinterpret_cast<__half2*>(&xy)[t] = hxy;
            reinterpret_cast<__half2*>(&yx)[t] = hyx;
            float rdd = ca * (0.25f * ca * (ba - rr) - rd);
            float* op = out + (size_t)(r0 + t) * 96;
            op[32 + lane] = rd;
            op[64 + lane] = rdd;
        }

        sXY[wib][q][lane] = xy;         // 1 STS.128 each
        sYX[wib][q][lane] = yx;
        __syncwarp();

        // split half2 accumulators: [t] over 4 rows; 0 = j<16, 1 = j>=16
        __half2 z = __floats2half2_rn(0.0f, 0.0f);
        __half2 aP0[4] = {z,z,z,z}, aP1[4] = {z,z,z,z};
        __half2 aQ0[4] = {z,z,z,z}, aQ1[4] = {z,z,z,z};

        #pragma unroll
        for (int j = 0; j < 16; j++) {
            __half2 ab = sAB[j * 32 + lane];            // LDS.32, conflict-free
            uint4 pxy = sXY[wib][q][j];                 // broadcast LDS.128
            uint4 pyx = sYX[wib][q][j];
            const __half2* hx = reinterpret_cast<const __half2*>(&pxy);
            const __half2* hy = reinterpret_cast<const __half2*>(&pyx);
            #pragma unroll
            for (int t = 0; t < 4; t++) {
                aP0[t] = __hfma2(ab, hx[t], aP0[t]);    // {ΣAx, ΣBy}
                aQ0[t] = __hfma2(ab, hy[t], aQ0[t]);    // {ΣAy, ΣBx}
            }
        }
        #pragma unroll
        for (int j = 16; j < 32; j++) {
            __half2 ab = sAB[j * 32 + lane];
            uint4 pxy = sXY[wib][q][j];
            uint4 pyx = sYX[wib][q][j];
            const __half2* hx = reinterpret_cast<const __half2*>(&pxy);
            const __half2* hy = reinterpret_cast<const __half2*>(&pyx);
            #pragma unroll
            for (int t = 0; t < 4; t++) {
                aP1[t] = __hfma2(ab, hx[t], aP1[t]);
                aQ1[t] = __hfma2(ab, hy[t], aQ1[t]);
            }
        }

        #pragma unroll
        for (int t = 0; t < 4; t++) {
            float2 p0 = __half22float2(aP0[t]);
            float2 p1 = __half22float2(aP1[t]);
            float2 q0 = __half22float2(aQ0[t]);
            float2 q1 = __half22float2(aQ1[t]);
            float P = (p0.x + p1.x) - (p0.y + p1.y);
            float Q = (q0.x + q1.x) + (q0.y + q1.y);
            out[(size_t)(r0 + t) * 96 + lane] = tpv + cv[t] * P - sv[t] * Q;
        }
    }
}

// ---------------- guarded tail kernel (remainder rows; unused at 65536) --------
__global__ void hopf_tail(const float* __restrict__ in, float* __restrict__ out,
                          int rowStart, int nrows) {
    const int tid  = threadIdx.x;
    const int lane = tid & 31;
    const int wib  = tid >> 5;

    __shared__ __half2 sAB[1024];
    __shared__ uint4   sXY[8][2][32];
    __shared__ uint4   sYX[8][2][32];

    {
        const float4* src = reinterpret_cast<const float4*>(gABh);
        float4*       dst = reinterpret_cast<float4*>(sAB);
        dst[tid] = src[tid];
    }
    const float tpv = gTPV[lane];
    const float ba  = gBA[lane];
    const float ca  = gCA[lane];
    __syncthreads();

    const int rowBase = rowStart + wib * 8;

    #pragma unroll
    for (int q = 0; q < 2; q++) {
        const int r0 = rowBase + q * 4;
        float sv[4], cv[4];
        uint4 xy, yx;

        #pragma unroll
        for (int t = 0; t < 4; t++) {
            const int row = r0 + t;
            float psi = 0.0f, rr = 0.0f, rd = 0.0f;
            if (row < nrows) {
                const float* rp = in + (size_t)row * 96;
                psi = rp[lane];  rr = rp[32 + lane];  rd = rp[64 + lane];
            }
            __sincosf(psi, &sv[t], &cv[t]);
            float x = rr * sv[t];
            float y = rr * cv[t];
            reinterpret_cast<__half2*>(&xy)[t] = __floats2half2_rn(x, y);
            reinterpret_cast<__half2*>(&yx)[t] = __floats2half2_rn(y, x);
            if (row < nrows) {
                float rdd = ca * (0.25f * ca * (ba - rr) - rd);
                float* op = out + (size_t)row * 96;
                op[32 + lane] = rd;
                op[64 + lane] = rdd;
            }
        }

        sXY[wib][q][lane] = xy;
        sYX[wib][q][lane] = yx;
        __syncwarp();

        __half2 z = __floats2half2_rn(0.0f, 0.0f);
        __half2 aP0[4] = {z,z,z,z}, aP1[4] = {z,z,z,z};
        __half2 aQ0[4] = {z,z,z,z}, aQ1[4] = {z,z,z,z};

        #pragma unroll
        for (int j = 0; j < 16; j++) {
            __half2 ab = sAB[j * 32 + lane];
            uint4 pxy = sXY[wib][q][j];
            uint4 pyx = sYX[wib][q][j];
            const __half2* hx = reinterpret_cast<const __half2*>(&pxy);
            const __half2* hy = reinterpret_cast<const __half2*>(&pyx);
            #pragma unroll
            for (int t = 0; t < 4; t++) {
                aP0[t] = __hfma2(ab, hx[t], aP0[t]);
                aQ0[t] = __hfma2(ab, hy[t], aQ0[t]);
            }
        }
        #pragma unroll
        for (int j = 16; j < 32; j++) {
            __half2 ab = sAB[j * 32 + lane];
            uint4 pxy = sXY[wib][q][j];
            uint4 pyx = sYX[wib][q][j];
            const __half2* hx = reinterpret_cast<const __half2*>(&pxy);
            const __half2* hy = reinterpret_cast<const __half2*>(&pyx);
            #pragma unroll
            for (int t = 0; t < 4; t++) {
                aP1[t] = __hfma2(ab, hx[t], aP1[t]);
                aQ1[t] = __hfma2(ab, hy[t], aQ1[t]);
            }
        }

        #pragma unroll
        for (int t = 0; t < 4; t++) {
            const int row = r0 + t;
            if (row < nrows) {
                float2 p0 = __half22float2(aP0[t]);
                float2 p1 = __half22float2(aP1[t]);
                float2 q0 = __half22float2(aQ0[t]);
                float2 q1 = __half22float2(aQ1[t]);
                float P = (p0.x + p1.x) - (p0.y + p1.y);
                float Q = (q0.x + q1.x) + (q0.y + q1.y);
                out[(size_t)row * 96 + lane] = tpv + cv[t] * P - sv[t] * Q;
            }
        }
    }
}

extern "C" void kernel_launch(void* const* d_in, const int* in_sizes, int n_in,
                              void* d_out, int out_size) {
    const float* states = (const float*)d_in[0];
    const float* v      = (const float*)d_in[1];
    const float* b      = (const float*)d_in[2];
    const float* c      = (const float*)d_in[3];
    const float* w      = (const float*)d_in[4];
    const float* phi    = (const float*)d_in[5];
    float* out = (float*)d_out;

    const int nrows = in_sizes[0] / 96;         // 65536
    prep_kernel<<<8, 128>>>(v, b, c, w, phi);

    const int fullBlocks = nrows / 64;          // 64 rows per 256-thread block
    if (fullBlocks > 0)
        hopf_kernel<<<fullBlocks, 256>>>(states, out);

    const int covered = fullBlocks * 64;
    if (covered < nrows)
        hopf_tail<<<1, 256>>>(states, out, covered, nrows);
}